// round 13
// baseline (speedup 1.0000x reference)
#include <cuda_runtime.h>
#include <math.h>

static constexpr int D = 512;          // feature dim (float32)
static constexpr int BLOCK = 256;      // 8 warps per block, 1 warp per edge

// Global accumulators (zero at module load; last block resets each launch).
__device__ float        g_sum;
__device__ unsigned int g_done;

// One warp per edge (proven ~53.5us mainloop — unchanged). Tail: each block's
// thread 0 folds its partial into g_sum with a RELAXED f32 atomic (plain
// ATOMG -> L2 op, NO membar, NO L1 flush), then increments a done-counter.
// The counter increment is control-dependent on the f32 atomic's RETURN
// value, so it cannot issue before the partial is globally visible at L2.
// The last block reads the total atomically and writes the mean.
__global__ void __launch_bounds__(BLOCK, 8) edge_loss_kernel(
    const float* __restrict__ feat,
    const int*   __restrict__ pos_src,
    const int*   __restrict__ pos_dst,
    const int*   __restrict__ neg_src,
    const int*   __restrict__ neg_dst,
    int e_pos, int e_total, int n_blocks, float inv_total,
    float* __restrict__ out)
{
    const int warp_global = (blockIdx.x * BLOCK + threadIdx.x) >> 5;
    const int lane = threadIdx.x & 31;
    const int wid  = threadIdx.x >> 5;

    float term = 0.0f;

    if (warp_global < e_total) {
        int s, d;
        const bool is_pos = (warp_global < e_pos);
        if (is_pos) {
            s = pos_src[warp_global];
            d = pos_dst[warp_global];
        } else {
            s = neg_src[warp_global - e_pos];
            d = neg_dst[warp_global - e_pos];
        }

        const float4* __restrict__ u =
            reinterpret_cast<const float4*>(feat + (size_t)s * D);
        const float4* __restrict__ v =
            reinterpret_cast<const float4*>(feat + (size_t)d * D);

        // 512 floats = 128 float4 per row; each lane takes 4 at stride 32.
        // All 8 vector loads issued up front for maximum MLP.
        float4 a0 = u[lane +  0];
        float4 a1 = u[lane + 32];
        float4 a2 = u[lane + 64];
        float4 a3 = u[lane + 96];
        float4 b0 = v[lane +  0];
        float4 b1 = v[lane + 32];
        float4 b2 = v[lane + 64];
        float4 b3 = v[lane + 96];

        float acc = 0.0f;
        acc = fmaf(a0.x, b0.x, acc); acc = fmaf(a0.y, b0.y, acc);
        acc = fmaf(a0.z, b0.z, acc); acc = fmaf(a0.w, b0.w, acc);
        acc = fmaf(a1.x, b1.x, acc); acc = fmaf(a1.y, b1.y, acc);
        acc = fmaf(a1.z, b1.z, acc); acc = fmaf(a1.w, b1.w, acc);
        acc = fmaf(a2.x, b2.x, acc); acc = fmaf(a2.y, b2.y, acc);
        acc = fmaf(a2.z, b2.z, acc); acc = fmaf(a2.w, b2.w, acc);
        acc = fmaf(a3.x, b3.x, acc); acc = fmaf(a3.y, b3.y, acc);
        acc = fmaf(a3.z, b3.z, acc); acc = fmaf(a3.w, b3.w, acc);

        // Warp reduce (deterministic tree).
        #pragma unroll
        for (int off = 16; off > 0; off >>= 1)
            acc += __shfl_xor_sync(0xffffffffu, acc, off);

        const float lab = is_pos ? 1.0f : 0.0f;
        term = fmaxf(acc, 0.0f) - acc * lab + log1pf(expf(-fabsf(acc)));
    }

    __shared__ float smem[BLOCK / 32];
    if (lane == 0) smem[wid] = term;
    __syncthreads();
    if (threadIdx.x != 0) return;         // 255 of 256 threads retire here

    // --- single thread per block from here ---
    float bsum = 0.0f;
    #pragma unroll
    for (int i = 0; i < BLOCK / 32; i++) bsum += smem[i];

    // Relaxed f32 atomic: payload + communication in one L2 op (no fence).
    float old = atomicAdd(&g_sum, bsum);

    // Control-depend the counter bump on the f32 atomic's completed result.
    // 0xDEADBEEF as f32 is ~-6.3e18 — unreachable by these sums, and opaque
    // to both nvcc and ptxas, so the dependency cannot be folded away.
    if (__float_as_uint(old) != 0xDEADBEEFu) {
        unsigned int cnt = atomicAdd(&g_done, 1u);
        if (cnt == (unsigned int)(n_blocks - 1)) {
            // All prior f32 adds are L2-visible (each preceded its block's
            // counter increment). Read the total atomically from L2.
            float total = atomicAdd(&g_sum, 0.0f);
            *out = total * inv_total;
            // Reset for the next graph replay (kernel boundary orders these).
            g_sum  = 0.0f;
            g_done = 0u;
        }
    }
}

extern "C" void kernel_launch(void* const* d_in, const int* in_sizes, int n_in,
                              void* d_out, int out_size)
{
    const float* feat    = (const float*)d_in[0];
    const int*   pos_src = (const int*)d_in[1];
    const int*   pos_dst = (const int*)d_in[2];
    const int*   neg_src = (const int*)d_in[3];
    const int*   neg_dst = (const int*)d_in[4];
    float* out = (float*)d_out;

    const int e_pos   = in_sizes[1];
    const int e_neg   = in_sizes[3];
    const int e_total = e_pos + e_neg;

    const int warps_per_block = BLOCK / 32;
    const int n_blocks = (e_total + warps_per_block - 1) / warps_per_block;

    edge_loss_kernel<<<n_blocks, BLOCK>>>(feat, pos_src, pos_dst,
                                          neg_src, neg_dst,
                                          e_pos, e_total, n_blocks,
                                          1.0f / (float)e_total, out);
}